// round 3
// baseline (speedup 1.0000x reference)
#include <cuda_runtime.h>

#define C_MAX 4096

// Scratch (no allocation allowed anywhere)
__device__ float  g_rnorm[C_MAX];
__device__ float  g_S[C_MAX];     // S[d] = sum_i m_i * rnorm_i * centers[i,d]
__device__ float  g_U[C_MAX];     // U[d] = sum_i h_i * rnorm_i * centers[i,d]
__device__ int    g_m[C_MAX];     // histogram of tlabel
__device__ int    g_h[C_MAX];     // histogram of label
__device__ double g_cl;           // sum of squared diffs for center loss

// ---------------------------------------------------------------------------
__device__ __forceinline__ float block_reduce_f(float v) {
    __shared__ float sh[32];
    #pragma unroll
    for (int o = 16; o; o >>= 1) v += __shfl_down_sync(0xffffffffu, v, o);
    int lane = threadIdx.x & 31, w = threadIdx.x >> 5;
    if (lane == 0) sh[w] = v;
    __syncthreads();
    int nw = blockDim.x >> 5;
    v = (threadIdx.x < (unsigned)nw) ? sh[threadIdx.x] : 0.f;
    if (w == 0) {
        #pragma unroll
        for (int o = 16; o; o >>= 1) v += __shfl_down_sync(0xffffffffu, v, o);
    }
    return v;  // valid in thread 0
}

// K0: zero scratch
__global__ void k_zero(int n) {
    for (int i = blockIdx.x * blockDim.x + threadIdx.x; i < n;
         i += gridDim.x * blockDim.x) {
        g_S[i] = 0.f; g_U[i] = 0.f; g_m[i] = 0; g_h[i] = 0;
    }
    if (blockIdx.x == 0 && threadIdx.x == 0) g_cl = 0.0;
}

// K1: histograms of label (size B) and tlabel (size C)
__global__ void k_hist(const int* __restrict__ label, int B,
                       const int* __restrict__ tlabel, int C) {
    int stride = gridDim.x * blockDim.x;
    for (int i = blockIdx.x * blockDim.x + threadIdx.x; i < B; i += stride)
        atomicAdd(&g_h[label[i]], 1);
    for (int i = blockIdx.x * blockDim.x + threadIdx.x; i < C; i += stride)
        atomicAdd(&g_m[tlabel[i]], 1);
}

// K2: per-row reciprocal norms of centers. One block per row.
__global__ void k_rnorm(const float* __restrict__ centers, int D) {
    int row = blockIdx.x;
    const float4* r4 = (const float4*)(centers + (size_t)row * D);
    int D4 = D >> 2;
    float s = 0.f;
    for (int j = threadIdx.x; j < D4; j += blockDim.x) {
        float4 v = r4[j];
        s += v.x * v.x + v.y * v.y + v.z * v.z + v.w * v.w;
    }
    float tot = block_reduce_f(s);
    if (threadIdx.x == 0) g_rnorm[row] = 1.f / sqrtf(tot);
}

// K3: weighted column sums S and U over centers.
// grid.x covers float4 columns, grid.y covers row chunks.
__global__ void k_su(const float* __restrict__ centers, int C, int D,
                     int rows_per_chunk) {
    int D4 = D >> 2;
    int c4 = blockIdx.x * blockDim.x + threadIdx.x;
    if (c4 >= D4) return;
    int r0 = blockIdx.y * rows_per_chunk;
    int r1 = min(r0 + rows_per_chunk, C);
    const float4* cen4 = (const float4*)centers;
    float4 s = {0.f, 0.f, 0.f, 0.f}, u = {0.f, 0.f, 0.f, 0.f};
    for (int i = r0; i < r1; i++) {
        float rn = g_rnorm[i];
        float wm = (float)g_m[i] * rn;
        float wh = (float)g_h[i] * rn;
        float4 v = cen4[(size_t)i * D4 + c4];
        s.x += wm * v.x; s.y += wm * v.y; s.z += wm * v.z; s.w += wm * v.w;
        u.x += wh * v.x; u.y += wh * v.y; u.z += wh * v.z; u.w += wh * v.w;
    }
    int c = c4 << 2;
    atomicAdd(&g_S[c + 0], s.x); atomicAdd(&g_S[c + 1], s.y);
    atomicAdd(&g_S[c + 2], s.z); atomicAdd(&g_S[c + 3], s.w);
    atomicAdd(&g_U[c + 0], u.x); atomicAdd(&g_U[c + 1], u.y);
    atomicAdd(&g_U[c + 2], u.z); atomicAdd(&g_U[c + 3], u.w);
}

// K4: center loss: sum over b,d of (feat - centers[label[b]])^2
__global__ __launch_bounds__(256, 8)
void k_cl(const float* __restrict__ feat,
          const float* __restrict__ centers,
          const int* __restrict__ label,
          int B, int D, int rows_per_block) {
    int D4 = D >> 2;
    const float4* f4 = (const float4*)feat;
    const float4* c4 = (const float4*)centers;
    float acc = 0.f;
    int r0 = blockIdx.x * rows_per_block;
    int r1 = min(r0 + rows_per_block, B);
    for (int r = r0; r < r1; r++) {
        int lab = __ldg(label + r);
        const float4* fr = f4 + (size_t)r * D4;
        const float4* cr = c4 + (size_t)lab * D4;
        for (int j = threadIdx.x; j < D4; j += blockDim.x) {
            float4 f = fr[j], c = cr[j];
            float dx = f.x - c.x, dy = f.y - c.y;
            float dz = f.z - c.z, dw = f.w - c.w;
            acc += dx * dx + dy * dy + dz * dz + dw * dw;
        }
    }
    float bs = block_reduce_f(acc);
    if (threadIdx.x == 0) atomicAdd(&g_cl, (double)bs);
}

// K5: finalize: out = lambda*(U.S + sum_i h_i*(C-2*m_i)) + 0.5*cl/B
__global__ void k_final(float* __restrict__ out, int B, int C, int D,
                        float tlambda) {
    double cacc = 0.0;  // integer-exact island constant part
    for (int i = threadIdx.x; i < C; i += blockDim.x)
        cacc += (double)g_h[i] * (double)(C - 2 * g_m[i]);
    double dacc = 0.0;  // U . S
    for (int d = threadIdx.x; d < D; d += blockDim.x)
        dacc += (double)g_U[d] * (double)g_S[d];

    __shared__ double sh1[32], sh2[32];
    #pragma unroll
    for (int o = 16; o; o >>= 1) {
        cacc += __shfl_down_sync(0xffffffffu, cacc, o);
        dacc += __shfl_down_sync(0xffffffffu, dacc, o);
    }
    int lane = threadIdx.x & 31, w = threadIdx.x >> 5;
    if (lane == 0) { sh1[w] = cacc; sh2[w] = dacc; }
    __syncthreads();
    int nw = blockDim.x >> 5;
    if (w == 0) {
        cacc = (threadIdx.x < (unsigned)nw) ? sh1[threadIdx.x] : 0.0;
        dacc = (threadIdx.x < (unsigned)nw) ? sh2[threadIdx.x] : 0.0;
        #pragma unroll
        for (int o = 16; o; o >>= 1) {
            cacc += __shfl_down_sync(0xffffffffu, cacc, o);
            dacc += __shfl_down_sync(0xffffffffu, dacc, o);
        }
        if (threadIdx.x == 0) {
            double island = (double)tlambda * (dacc + cacc);
            double cl = 0.5 * g_cl / (double)B;
            out[0] = (float)(island + cl);
        }
    }
}

extern "C" void kernel_launch(void* const* d_in, const int* in_sizes, int n_in,
                              void* d_out, int out_size) {
    const int*   label   = (const int*)d_in[0];
    const float* feat    = (const float*)d_in[1];
    const int*   tlabel  = (const int*)d_in[2];
    const float* centers = (const float*)d_in[3];
    float*       out     = (float*)d_out;

    int B = in_sizes[0];
    int C = in_sizes[2];
    int D = in_sizes[1] / B;
    int D4 = D >> 2;

    const float TLAMBDA = 0.01f;

    // K0: zero scratch
    k_zero<<<(C_MAX + 255) / 256, 256>>>(C_MAX);

    // K1: histograms
    {
        int histN = (B > C) ? B : C;
        k_hist<<<(histN + 255) / 256, 256>>>(label, B, tlabel, C);
    }

    // K2: rnorm (one block per center row)
    k_rnorm<<<C, 256>>>(centers, D);

    // K3: weighted column sums (S, U)
    {
        const int ROWS_PER_CHUNK = 128;
        dim3 grid((D4 + 127) / 128, (C + ROWS_PER_CHUNK - 1) / ROWS_PER_CHUNK);
        k_su<<<grid, 128>>>(centers, C, D, ROWS_PER_CHUNK);
    }

    // K4: center loss (dominant pass: reads all of feat)
    {
        const int ROWS_PER_BLOCK = 16;
        int nblk = (B + ROWS_PER_BLOCK - 1) / ROWS_PER_BLOCK;
        k_cl<<<nblk, 256>>>(feat, centers, label, B, D, ROWS_PER_BLOCK);
    }

    // K5: finalize
    k_final<<<1, 256>>>(out, B, C, D, TLAMBDA);
}

// round 4
// speedup vs baseline: 1.4033x; 1.4033x over previous
#include <cuda_runtime.h>

#define C_MAX 4096

// Scratch (no allocation allowed anywhere)
__device__ float  g_rnorm[C_MAX];
__device__ float  g_S[C_MAX];     // S[d] = sum_i m_i * rnorm_i * centers[i,d]
__device__ float  g_U[C_MAX];     // U[d] = sum_i h_i * rnorm_i * centers[i,d]
__device__ int    g_m[C_MAX];     // histogram of tlabel
__device__ int    g_h[C_MAX];     // histogram of label
__device__ double g_cl;           // sum of squared diffs for center loss

// ---------------------------------------------------------------------------
__device__ __forceinline__ float block_reduce_f(float v) {
    __shared__ float sh[32];
    #pragma unroll
    for (int o = 16; o; o >>= 1) v += __shfl_down_sync(0xffffffffu, v, o);
    int lane = threadIdx.x & 31, w = threadIdx.x >> 5;
    if (lane == 0) sh[w] = v;
    __syncthreads();
    int nw = blockDim.x >> 5;
    v = (threadIdx.x < (unsigned)nw) ? sh[threadIdx.x] : 0.f;
    if (w == 0) {
        #pragma unroll
        for (int o = 16; o; o >>= 1) v += __shfl_down_sync(0xffffffffu, v, o);
    }
    return v;  // valid in thread 0
}

// K0: zero scratch
__global__ void k_zero(int n) {
    for (int i = blockIdx.x * blockDim.x + threadIdx.x; i < n;
         i += gridDim.x * blockDim.x) {
        g_S[i] = 0.f; g_U[i] = 0.f; g_m[i] = 0; g_h[i] = 0;
    }
    if (blockIdx.x == 0 && threadIdx.x == 0) g_cl = 0.0;
}

// K1: histograms of label (size B) and tlabel (size C)
__global__ void k_hist(const int* __restrict__ label, int B,
                       const int* __restrict__ tlabel, int C) {
    int stride = gridDim.x * blockDim.x;
    for (int i = blockIdx.x * blockDim.x + threadIdx.x; i < B; i += stride)
        atomicAdd(&g_h[label[i]], 1);
    for (int i = blockIdx.x * blockDim.x + threadIdx.x; i < C; i += stride)
        atomicAdd(&g_m[tlabel[i]], 1);
}

// K2: per-row reciprocal norms of centers. One block per row.
__global__ void k_rnorm(const float* __restrict__ centers, int D) {
    int row = blockIdx.x;
    const float4* r4 = (const float4*)(centers + (size_t)row * D);
    int D4 = D >> 2;
    float s = 0.f;
    for (int j = threadIdx.x; j < D4; j += blockDim.x) {
        float4 v = r4[j];
        s += v.x * v.x + v.y * v.y + v.z * v.z + v.w * v.w;
    }
    float tot = block_reduce_f(s);
    if (threadIdx.x == 0) g_rnorm[row] = 1.f / sqrtf(tot);
}

// K3: weighted column sums S and U over centers.
// grid.x covers float4 columns, grid.y covers row chunks.
// ROWS_PER_CHUNK small (16) so the grid is large enough to saturate DRAM.
template <int RPC>
__global__ __launch_bounds__(128)
void k_su(const float* __restrict__ centers, int C, int D) {
    int D4 = D >> 2;
    int c4 = blockIdx.x * blockDim.x + threadIdx.x;
    if (c4 >= D4) return;
    int r0 = blockIdx.y * RPC;
    const float4* cen4 = (const float4*)centers + (size_t)r0 * D4 + c4;
    float4 s = {0.f, 0.f, 0.f, 0.f}, u = {0.f, 0.f, 0.f, 0.f};
    #pragma unroll 4
    for (int k = 0; k < RPC; k++) {
        int i = r0 + k;
        float rn = g_rnorm[i];
        float wm = (float)g_m[i] * rn;
        float wh = (float)g_h[i] * rn;
        float4 v = cen4[(size_t)k * D4];
        s.x += wm * v.x; s.y += wm * v.y; s.z += wm * v.z; s.w += wm * v.w;
        u.x += wh * v.x; u.y += wh * v.y; u.z += wh * v.z; u.w += wh * v.w;
    }
    int c = c4 << 2;
    atomicAdd(&g_S[c + 0], s.x); atomicAdd(&g_S[c + 1], s.y);
    atomicAdd(&g_S[c + 2], s.z); atomicAdd(&g_S[c + 3], s.w);
    atomicAdd(&g_U[c + 0], u.x); atomicAdd(&g_U[c + 1], u.y);
    atomicAdd(&g_U[c + 2], u.z); atomicAdd(&g_U[c + 3], u.w);
}

// K4: center loss: sum over b,d of (feat - centers[label[b]])^2
__global__ __launch_bounds__(256, 8)
void k_cl(const float* __restrict__ feat,
          const float* __restrict__ centers,
          const int* __restrict__ label,
          int B, int D, int rows_per_block) {
    int D4 = D >> 2;
    const float4* f4 = (const float4*)feat;
    const float4* c4 = (const float4*)centers;
    float acc = 0.f;
    int r0 = blockIdx.x * rows_per_block;
    int r1 = min(r0 + rows_per_block, B);
    for (int r = r0; r < r1; r++) {
        int lab = __ldg(label + r);
        const float4* fr = f4 + (size_t)r * D4;
        const float4* cr = c4 + (size_t)lab * D4;
        #pragma unroll 2
        for (int j = threadIdx.x; j < D4; j += blockDim.x) {
            float4 f = fr[j], c = cr[j];
            float dx = f.x - c.x, dy = f.y - c.y;
            float dz = f.z - c.z, dw = f.w - c.w;
            acc += dx * dx + dy * dy + dz * dz + dw * dw;
        }
    }
    float bs = block_reduce_f(acc);
    if (threadIdx.x == 0) atomicAdd(&g_cl, (double)bs);
}

// K5: finalize: out = lambda*(U.S + sum_i h_i*(C-2*m_i)) + 0.5*cl/B
__global__ void k_final(float* __restrict__ out, int B, int C, int D,
                        float tlambda) {
    double cacc = 0.0;  // integer-exact island constant part
    for (int i = threadIdx.x; i < C; i += blockDim.x)
        cacc += (double)g_h[i] * (double)(C - 2 * g_m[i]);
    double dacc = 0.0;  // U . S
    for (int d = threadIdx.x; d < D; d += blockDim.x)
        dacc += (double)g_U[d] * (double)g_S[d];

    __shared__ double sh1[32], sh2[32];
    #pragma unroll
    for (int o = 16; o; o >>= 1) {
        cacc += __shfl_down_sync(0xffffffffu, cacc, o);
        dacc += __shfl_down_sync(0xffffffffu, dacc, o);
    }
    int lane = threadIdx.x & 31, w = threadIdx.x >> 5;
    if (lane == 0) { sh1[w] = cacc; sh2[w] = dacc; }
    __syncthreads();
    int nw = blockDim.x >> 5;
    if (w == 0) {
        cacc = (threadIdx.x < (unsigned)nw) ? sh1[threadIdx.x] : 0.0;
        dacc = (threadIdx.x < (unsigned)nw) ? sh2[threadIdx.x] : 0.0;
        #pragma unroll
        for (int o = 16; o; o >>= 1) {
            cacc += __shfl_down_sync(0xffffffffu, cacc, o);
            dacc += __shfl_down_sync(0xffffffffu, dacc, o);
        }
        if (threadIdx.x == 0) {
            double island = (double)tlambda * (dacc + cacc);
            double cl = 0.5 * g_cl / (double)B;
            out[0] = (float)(island + cl);
        }
    }
}

extern "C" void kernel_launch(void* const* d_in, const int* in_sizes, int n_in,
                              void* d_out, int out_size) {
    const int*   label   = (const int*)d_in[0];
    const float* feat    = (const float*)d_in[1];
    const int*   tlabel  = (const int*)d_in[2];
    const float* centers = (const float*)d_in[3];
    float*       out     = (float*)d_out;

    int B = in_sizes[0];
    int C = in_sizes[2];
    int D = in_sizes[1] / B;
    int D4 = D >> 2;

    const float TLAMBDA = 0.01f;

    // K0: zero scratch
    k_zero<<<(C_MAX + 255) / 256, 256>>>(C_MAX);

    // K1: histograms
    {
        int histN = (B > C) ? B : C;
        k_hist<<<(histN + 255) / 256, 256>>>(label, B, tlabel, C);
    }

    // K2: rnorm (one block per center row)
    k_rnorm<<<C, 256>>>(centers, D);

    // K3: weighted column sums (S, U) — many small row chunks for DRAM MLP
    {
        constexpr int RPC = 16;
        dim3 grid((D4 + 127) / 128, (C + RPC - 1) / RPC);
        k_su<RPC><<<grid, 128>>>(centers, C, D);
    }

    // K4: center loss (dominant pass: reads all of feat)
    {
        const int ROWS_PER_BLOCK = 8;
        int nblk = (B + ROWS_PER_BLOCK - 1) / ROWS_PER_BLOCK;
        k_cl<<<nblk, 256>>>(feat, centers, label, B, D, ROWS_PER_BLOCK);
    }

    // K5: finalize
    k_final<<<1, 256>>>(out, B, C, D, TLAMBDA);
}

// round 5
// speedup vs baseline: 1.4066x; 1.0023x over previous
#include <cuda_runtime.h>

#define C_MAX 4096

// Scratch (no allocation allowed anywhere)
__device__ float  g_rnorm[C_MAX];
__device__ float  g_S[C_MAX];     // S[d] = sum_i m_i * rnorm_i * centers[i,d]
__device__ float  g_U[C_MAX];     // U[d] = sum_i h_i * rnorm_i * centers[i,d]
__device__ int    g_m[C_MAX];     // histogram of tlabel
__device__ int    g_h[C_MAX];     // histogram of label
__device__ double g_cl;           // sum of squared diffs for center loss

// ---------------------------------------------------------------------------
__device__ __forceinline__ float block_reduce_f(float v) {
    __shared__ float sh[32];
    #pragma unroll
    for (int o = 16; o; o >>= 1) v += __shfl_down_sync(0xffffffffu, v, o);
    int lane = threadIdx.x & 31, w = threadIdx.x >> 5;
    if (lane == 0) sh[w] = v;
    __syncthreads();
    int nw = blockDim.x >> 5;
    v = (threadIdx.x < (unsigned)nw) ? sh[threadIdx.x] : 0.f;
    if (w == 0) {
        #pragma unroll
        for (int o = 16; o; o >>= 1) v += __shfl_down_sync(0xffffffffu, v, o);
    }
    return v;  // valid in thread 0
}

// K0: zero scratch
__global__ void k_zero(int n) {
    for (int i = blockIdx.x * blockDim.x + threadIdx.x; i < n;
         i += gridDim.x * blockDim.x) {
        g_S[i] = 0.f; g_U[i] = 0.f; g_m[i] = 0; g_h[i] = 0;
    }
    if (blockIdx.x == 0 && threadIdx.x == 0) g_cl = 0.0;
}

// K1: histograms of label (size B) and tlabel (size C)
__global__ void k_hist(const int* __restrict__ label, int B,
                       const int* __restrict__ tlabel, int C) {
    int stride = gridDim.x * blockDim.x;
    for (int i = blockIdx.x * blockDim.x + threadIdx.x; i < B; i += stride)
        atomicAdd(&g_h[label[i]], 1);
    for (int i = blockIdx.x * blockDim.x + threadIdx.x; i < C; i += stride)
        atomicAdd(&g_m[tlabel[i]], 1);
}

// K2: per-row reciprocal norms of centers. One block per row.
__global__ void k_rnorm(const float* __restrict__ centers, int D) {
    int row = blockIdx.x;
    const float4* r4 = (const float4*)(centers + (size_t)row * D);
    int D4 = D >> 2;
    float s = 0.f;
    for (int j = threadIdx.x; j < D4; j += blockDim.x) {
        float4 v = r4[j];
        s += v.x * v.x + v.y * v.y + v.z * v.z + v.w * v.w;
    }
    float tot = block_reduce_f(s);
    if (threadIdx.x == 0) g_rnorm[row] = 1.f / sqrtf(tot);
}

// K3: weighted column sums S and U over centers.
// grid.x covers float4 columns, grid.y covers row chunks.
// ROWS_PER_CHUNK small (16) so the grid is large enough to saturate DRAM.
template <int RPC>
__global__ __launch_bounds__(128)
void k_su(const float* __restrict__ centers, int C, int D) {
    int D4 = D >> 2;
    int c4 = blockIdx.x * blockDim.x + threadIdx.x;
    if (c4 >= D4) return;
    int r0 = blockIdx.y * RPC;
    const float4* cen4 = (const float4*)centers + (size_t)r0 * D4 + c4;
    float4 s = {0.f, 0.f, 0.f, 0.f}, u = {0.f, 0.f, 0.f, 0.f};
    #pragma unroll 4
    for (int k = 0; k < RPC; k++) {
        int i = r0 + k;
        float rn = g_rnorm[i];
        float wm = (float)g_m[i] * rn;
        float wh = (float)g_h[i] * rn;
        float4 v = cen4[(size_t)k * D4];
        s.x += wm * v.x; s.y += wm * v.y; s.z += wm * v.z; s.w += wm * v.w;
        u.x += wh * v.x; u.y += wh * v.y; u.z += wh * v.z; u.w += wh * v.w;
    }
    int c = c4 << 2;
    atomicAdd(&g_S[c + 0], s.x); atomicAdd(&g_S[c + 1], s.y);
    atomicAdd(&g_S[c + 2], s.z); atomicAdd(&g_S[c + 3], s.w);
    atomicAdd(&g_U[c + 0], u.x); atomicAdd(&g_U[c + 1], u.y);
    atomicAdd(&g_U[c + 2], u.z); atomicAdd(&g_U[c + 3], u.w);
}

// K4: center loss: sum over b,d of (feat - centers[label[b]])^2
__global__ __launch_bounds__(256, 8)
void k_cl(const float* __restrict__ feat,
          const float* __restrict__ centers,
          const int* __restrict__ label,
          int B, int D, int rows_per_block) {
    int D4 = D >> 2;
    const float4* f4 = (const float4*)feat;
    const float4* c4 = (const float4*)centers;
    float acc = 0.f;
    int r0 = blockIdx.x * rows_per_block;
    int r1 = min(r0 + rows_per_block, B);
    for (int r = r0; r < r1; r++) {
        int lab = __ldg(label + r);
        const float4* fr = f4 + (size_t)r * D4;
        const float4* cr = c4 + (size_t)lab * D4;
        #pragma unroll 2
        for (int j = threadIdx.x; j < D4; j += blockDim.x) {
            float4 f = fr[j], c = cr[j];
            float dx = f.x - c.x, dy = f.y - c.y;
            float dz = f.z - c.z, dw = f.w - c.w;
            acc += dx * dx + dy * dy + dz * dz + dw * dw;
        }
    }
    float bs = block_reduce_f(acc);
    if (threadIdx.x == 0) atomicAdd(&g_cl, (double)bs);
}

// K5: finalize: out = lambda*(U.S + sum_i h_i*(C-2*m_i)) + 0.5*cl/B
__global__ void k_final(float* __restrict__ out, int B, int C, int D,
                        float tlambda) {
    double cacc = 0.0;  // integer-exact island constant part
    for (int i = threadIdx.x; i < C; i += blockDim.x)
        cacc += (double)g_h[i] * (double)(C - 2 * g_m[i]);
    double dacc = 0.0;  // U . S
    for (int d = threadIdx.x; d < D; d += blockDim.x)
        dacc += (double)g_U[d] * (double)g_S[d];

    __shared__ double sh1[32], sh2[32];
    #pragma unroll
    for (int o = 16; o; o >>= 1) {
        cacc += __shfl_down_sync(0xffffffffu, cacc, o);
        dacc += __shfl_down_sync(0xffffffffu, dacc, o);
    }
    int lane = threadIdx.x & 31, w = threadIdx.x >> 5;
    if (lane == 0) { sh1[w] = cacc; sh2[w] = dacc; }
    __syncthreads();
    int nw = blockDim.x >> 5;
    if (w == 0) {
        cacc = (threadIdx.x < (unsigned)nw) ? sh1[threadIdx.x] : 0.0;
        dacc = (threadIdx.x < (unsigned)nw) ? sh2[threadIdx.x] : 0.0;
        #pragma unroll
        for (int o = 16; o; o >>= 1) {
            cacc += __shfl_down_sync(0xffffffffu, cacc, o);
            dacc += __shfl_down_sync(0xffffffffu, dacc, o);
        }
        if (threadIdx.x == 0) {
            double island = (double)tlambda * (dacc + cacc);
            double cl = 0.5 * g_cl / (double)B;
            out[0] = (float)(island + cl);
        }
    }
}

extern "C" void kernel_launch(void* const* d_in, const int* in_sizes, int n_in,
                              void* d_out, int out_size) {
    const int*   label   = (const int*)d_in[0];
    const float* feat    = (const float*)d_in[1];
    const int*   tlabel  = (const int*)d_in[2];
    const float* centers = (const float*)d_in[3];
    float*       out     = (float*)d_out;

    int B = in_sizes[0];
    int C = in_sizes[2];
    int D = in_sizes[1] / B;
    int D4 = D >> 2;

    const float TLAMBDA = 0.01f;

    // K0: zero scratch
    k_zero<<<(C_MAX + 255) / 256, 256>>>(C_MAX);

    // K1: histograms
    {
        int histN = (B > C) ? B : C;
        k_hist<<<(histN + 255) / 256, 256>>>(label, B, tlabel, C);
    }

    // K2: rnorm (one block per center row)
    k_rnorm<<<C, 256>>>(centers, D);

    // K3: weighted column sums (S, U) — many small row chunks for DRAM MLP
    {
        constexpr int RPC = 16;
        dim3 grid((D4 + 127) / 128, (C + RPC - 1) / RPC);
        k_su<RPC><<<grid, 128>>>(centers, C, D);
    }

    // K4: center loss (dominant pass: reads all of feat)
    {
        const int ROWS_PER_BLOCK = 8;
        int nblk = (B + ROWS_PER_BLOCK - 1) / ROWS_PER_BLOCK;
        k_cl<<<nblk, 256>>>(feat, centers, label, B, D, ROWS_PER_BLOCK);
    }

    // K5: finalize
    k_final<<<1, 256>>>(out, B, C, D, TLAMBDA);
}